// round 17
// baseline (speedup 1.0000x reference)
#include <cuda_runtime.h>
#include <math.h>

#define T_STEPS 1024
#define NB 128
#define FD 128
#define HD 128

// Scratch: 8 precomputed floats per (b,t):
//  [0:4) = x_t @ W_in_x^T + b_in   (x-part of y)
//  [4:8) = vqc(x_t @ W_x^T + b_x, vqc_w[2])  (fully h-independent)
__device__ float g_xpre[NB * T_STEPS * 8];

typedef unsigned long long u64;

__device__ __forceinline__ u64 pack2(float lo, float hi) {
    u64 r;
    asm("mov.b64 %0, {%1, %2};" : "=l"(r) : "f"(lo), "f"(hi));
    return r;
}
__device__ __forceinline__ void unpack2(u64 v, float& lo, float& hi) {
    asm("mov.b64 {%0, %1}, %2;" : "=f"(lo), "=f"(hi) : "l"(v));
}
__device__ __forceinline__ u64 fma2(u64 a, u64 b, u64 c) {
    u64 r;
    asm("fma.rn.f32x2 %0, %1, %2, %3;" : "=l"(r) : "l"(a), "l"(b), "l"(c));
    return r;
}
__device__ __forceinline__ u64 add2(u64 a, u64 b) {
    u64 r;
    asm("add.rn.f32x2 %0, %1, %2;" : "=l"(r) : "l"(a), "l"(b));
    return r;
}
__device__ __forceinline__ float ex2f(float x) {
    float r;
    asm("ex2.approx.f32 %0, %1;" : "=f"(r) : "f"(x));
    return r;
}
__device__ __forceinline__ float rcpf(float x) {
    float r;
    asm("rcp.approx.f32 %0, %1;" : "=f"(r) : "f"(x));
    return r;
}

// ---------------------------------------------------------------------------
// Pre-pass v4: TWO rows per iteration via HALF-WARPS. Row A on lanes 0-15,
// row B on lanes 16-31 (consecutive rows -> coalesced LDG). Each lane covers
// 8 x-columns of its own row; the butterfly runs inside the half-warp with
// masks 8/4/2/1: 8 shuffle-sends per pair (4/row) vs 16 in the xor16 scheme.
// Final layout (k on bits 3:1, dup on bit0, row on bit4) matches the proven
// pair-product trick (masks 2, 4 — never cross the half-warp).
// MIO/row: 11 -> 7.
// ---------------------------------------------------------------------------
#define PP_WARPS 8192

__global__ void __launch_bounds__(256) qgru_prepass(
    const float* __restrict__ x,
    const float* __restrict__ W_in, const float* __restrict__ b_in,
    const float* __restrict__ W_x,  const float* __restrict__ b_x,
    const float* __restrict__ vqc_w)
{
    const int lane = threadIdx.x & 31;
    const int gw   = (blockIdx.x * blockDim.x + threadIdx.x) >> 5;  // 0..8191
    const int hw   = lane >> 4;           // row within pair (0=A, 1=B)
    const int s    = lane & 15;           // col chunk [8s, 8s+8)
    const int b3   = (lane >> 3) & 1;
    const int b2   = (lane >> 2) & 1;
    const int b1   = (lane >> 1) & 1;
    const int k    = b3 * 4 + b2 * 2 + b1;   // owned sum 0..7
    const int ci   = b2 * 2 + b1;            // cosine index for k>=4 lanes

    // packed weight pairs: sum kk over x[8s .. 8s+8)
    u64 wt[8][4];
#pragma unroll
    for (int kk = 0; kk < 8; kk++) {
        const float* row = (kk < 4) ? (W_in + kk * (HD + FD) + HD)
                                    : (W_x + (kk - 4) * FD);
        float4 w0 = *reinterpret_cast<const float4*>(row + 8 * s);
        float4 w1 = *reinterpret_cast<const float4*>(row + 8 * s + 4);
        wt[kk][0] = pack2(w0.x, w0.y);
        wt[kk][1] = pack2(w0.z, w0.w);
        wt[kk][2] = pack2(w1.x, w1.y);
        wt[kk][3] = pack2(w1.z, w1.w);
    }
    // bias for the owned sum (k>=4 folds in vqc_w[2] for the cosine arg)
    const float bias_l = (k < 4) ? b_in[k]
                                 : (b_x[k - 4] + vqc_w[8 + (k - 4)]);

    const float* xrp = x + 8 * s;     // this lane's col base; + row*FD per row

    // process one PAIR of consecutive rows (row = pairRow0 + hw per half-warp)
    auto process = [&](float4 xv0, float4 xv1, int pairRow0) {
        u64 x0 = pack2(xv0.x, xv0.y), x1 = pack2(xv0.z, xv0.w);
        u64 x2 = pack2(xv1.x, xv1.y), x3 = pack2(xv1.z, xv1.w);

        float v[8];
#pragma unroll
        for (int kk = 0; kk < 8; kk++) {
            u64 acc = fma2(x0, wt[kk][0],
                      fma2(x1, wt[kk][1],
                      fma2(x2, wt[kk][2],
                      fma2(x3, wt[kk][3], 0ull))));
            float lo, hi;
            unpack2(acc, lo, hi);
            v[kk] = lo + hi;
        }

        // 4-round half-warp value-splitting butterfly (8 sends)
        float w4[4];
#pragma unroll
        for (int i = 0; i < 4; i++) {
            float send = b3 ? v[i] : v[4 + i];
            float recv = __shfl_xor_sync(0xffffffffu, send, 8);
            w4[i] = (b3 ? v[4 + i] : v[i]) + recv;
        }
        float w2[2];
#pragma unroll
        for (int i = 0; i < 2; i++) {
            float send = b2 ? w4[i] : w4[2 + i];
            float recv = __shfl_xor_sync(0xffffffffu, send, 4);
            w2[i] = (b2 ? w4[2 + i] : w4[i]) + recv;
        }
        float w1v;
        {
            float send = b1 ? w2[0] : w2[1];
            float recv = __shfl_xor_sync(0xffffffffu, send, 2);
            w1v = (b1 ? w2[1] : w2[0]) + recv;
        }
        float sfull = w1v + __shfl_xor_sync(0xffffffffu, w1v, 1);
        // sum k replicated over bit0 pairs, per half-warp row

        float val = sfull + bias_l;
        float cv  = __cosf(val);               // meaningful for k>=4 lanes

        // pair-product trick (within half-warp; masks 2, 4)
        float cp = __shfl_xor_sync(0xffffffffu, cv, 2);
        float pp = cv * cp;
        float po = __shfl_xor_sync(0xffffffffu, pp, 4);
        float prod = (ci == 0) ? cp * po
                   : (ci == 1) ? pp
                   : (ci == 2) ? po * cv
                               : po * pp;

        if ((lane & 1) == 0) {
            float sval = (k < 4) ? val : prod;
            g_xpre[(size_t)(pairRow0 + hw) * 8 + k] = sval;
        }
    };

    // 16 rows/warp: 8 pair-iterations, pairs gw + m*PP_WARPS, double-buffered
    {
        int r0 = 2 * gw + hw;
        float4 a0 = *reinterpret_cast<const float4*>(xrp + (size_t)r0 * FD);
        float4 a1 = *reinterpret_cast<const float4*>(xrp + (size_t)r0 * FD + 4);

#pragma unroll 1
        for (int m = 0; m < 8; m++) {
            float4 n0, n1;
            if (m < 7) {
                int rn = 2 * (gw + (m + 1) * PP_WARPS) + hw;
                n0 = *reinterpret_cast<const float4*>(xrp + (size_t)rn * FD);
                n1 = *reinterpret_cast<const float4*>(xrp + (size_t)rn * FD + 4);
            }
            process(a0, a1, 2 * (gw + m * PP_WARPS));
            a0 = n0; a1 = n1;
        }
    }
}

// ---------------------------------------------------------------------------
// Sequential recurrence (R13/R16 version — FROZEN, proven 252.4us):
// 1 CTA per batch row, 128 threads; thread j owns h_j in a register.
//  - 8 FMUL partials, 3-round value-split butterfly
//  - 32 STS into padded psum rows (stride 20, conflict-free)
//  - barrier; each lane reads its sum's 16 partials (4x LDS.128) + add2 tree
//  - one warp-wide MUFU.COS -> 12 gate cosines via 12 direct shfl.idx
//  - ex2-folded merged-division GRU update
// ---------------------------------------------------------------------------
__global__ void __launch_bounds__(128, 1) qgru_seq(
    const float* __restrict__ W_in, const float* __restrict__ W_h,
    const float* __restrict__ b_h,
    const float* __restrict__ W_out, const float* __restrict__ b_out,
    const float* __restrict__ vqc_w,
    float* __restrict__ out)
{
    const int b    = blockIdx.x;
    const int j    = threadIdx.x;
    const int lane = j & 31;
    const int w    = j >> 5;
    const int k    = lane >> 2;   // owned sum index after 3-round butterfly
    const int q    = lane & 3;    // partial index this lane holds

    __shared__ __align__(16) float xs[T_STEPS * 8];   // 32 KB staged xpre row
    __shared__ __align__(16) float psum[2][8 * 20];   // padded: row k at k*20

    // ---- stage this row's xpre into smem
    {
        const float4* src = reinterpret_cast<const float4*>(
            g_xpre + (size_t)b * T_STEPS * 8);
        float4* dst = reinterpret_cast<float4*>(xs);
        float4 tmp[16];
#pragma unroll
        for (int i = 0; i < 16; i++) tmp[i] = src[j + 128 * i];
#pragma unroll
        for (int i = 0; i < 16; i++) dst[j + 128 * i] = tmp[i];
    }

    // ---- dot weights: wk[kk] = row_kk[j]  (thread j's h column)
    float wk[8];
#pragma unroll
    for (int kk = 0; kk < 8; kk++) {
        const float* row = (kk < 4) ? (W_in + kk * (HD + FD))
                                    : (W_h + (kk - 4) * HD);
        wk[kk] = row[j];
    }

    // W_out prescaled: RZ by log2e (exp(-o)), HX by 2*log2e (exp(-2u))
    const float L2E = 1.4426950408889634f;
    float woRZ[4], woHX[4];
#pragma unroll
    for (int kk = 0; kk < 4; kk++) {
        float wv = W_out[j * 4 + kk];
        woRZ[kk] = wv * L2E;
        woHX[kk] = wv * (2.0f * L2E);
    }
    const float bof  = b_out[j];
    const float boRZ = bof * L2E;
    const float boHX = bof * (2.0f * L2E);

    // ---- cosine role (loop-invariant): quad k, member q
    float cadd = 0.0f;
    if (k < 4) {
        if (q == 0)      cadd = vqc_w[k];
        else if (q == 1) cadd = vqc_w[4 + k];
    } else if (q == 0) {
        cadd = vqc_w[12 + (k - 4)] + b_h[k - 4];
    }
    const bool use_p = (k < 4);

    const int hi = (lane >> 4) & 1;
    const int h3 = (lane >> 3) & 1;
    const int h2 = (lane >> 2) & 1;

    float hj = 0.0f;                 // h_j lives here; never leaves registers

    // c_last = zeros
    out[(size_t)NB * T_STEPS * HD + (size_t)NB * HD + b * HD + j] = 0.0f;

    float* __restrict__ orow = out + (size_t)b * T_STEPS * HD + j;
    const int pslot = k * 20 + w * 4 + q;   // this lane's psum store index

    __syncthreads();   // xs staged

#pragma unroll 1
    for (int t = 0; t < T_STEPS; t++) {
        // ---- pre-barrier: warp-partial dots over this warp's own h slice
        float v[8];
#pragma unroll
        for (int kk = 0; kk < 8; kk++) v[kk] = wk[kk] * hj;

        // 3-round value-splitting butterfly: lane ends with one partial
        // (sum k=lane>>2, over the 8 lanes sharing lane&3)
        float u4_0, u4_1, u4_2, u4_3;
        {
            float s0 = hi ? v[0] : v[4];
            float s1 = hi ? v[1] : v[5];
            float s2 = hi ? v[2] : v[6];
            float s3 = hi ? v[3] : v[7];
            float r0 = __shfl_xor_sync(0xffffffffu, s0, 16);
            float r1 = __shfl_xor_sync(0xffffffffu, s1, 16);
            float r2 = __shfl_xor_sync(0xffffffffu, s2, 16);
            float r3 = __shfl_xor_sync(0xffffffffu, s3, 16);
            u4_0 = (hi ? v[4] : v[0]) + r0;
            u4_1 = (hi ? v[5] : v[1]) + r1;
            u4_2 = (hi ? v[6] : v[2]) + r2;
            u4_3 = (hi ? v[7] : v[3]) + r3;
        }
        float u2_0, u2_1;
        {
            float s0 = h3 ? u4_0 : u4_2;
            float s1 = h3 ? u4_1 : u4_3;
            float r0 = __shfl_xor_sync(0xffffffffu, s0, 8);
            float r1 = __shfl_xor_sync(0xffffffffu, s1, 8);
            u2_0 = (h3 ? u4_2 : u4_0) + r0;
            u2_1 = (h3 ? u4_3 : u4_1) + r1;
        }
        float s;
        {
            float s0 = h2 ? u2_0 : u2_1;
            float r0 = __shfl_xor_sync(0xffffffffu, s0, 4);
            s = (h2 ? u2_1 : u2_0) + r0;
        }

        psum[t & 1][pslot] = s;      // all 32 lanes store (conflict-free)

        // psum-independent work overlapping the barrier region
        float4 P1 = *reinterpret_cast<const float4*>(xs + t * 8 + 4);
        float pc  = xs[t * 8 + (k & 3)];
        float o_x = fmaf(P1.x, woHX[0],
                    fmaf(P1.y, woHX[1], fmaf(P1.z, woHX[2],
                    fmaf(P1.w, woHX[3], boHX))));

        __syncthreads();

        // ---- post-barrier: total for owned sum k (16 partials, add2 tree)
        const float* prow = psum[t & 1] + k * 20;
        ulonglong2 A = *reinterpret_cast<const ulonglong2*>(prow + 0);
        ulonglong2 B = *reinterpret_cast<const ulonglong2*>(prow + 4);
        ulonglong2 C = *reinterpret_cast<const ulonglong2*>(prow + 8);
        ulonglong2 D = *reinterpret_cast<const ulonglong2*>(prow + 12);
        u64 e0 = add2(A.x, A.y);
        u64 e1 = add2(B.x, B.y);
        u64 e2 = add2(C.x, C.y);
        u64 e3 = add2(D.x, D.y);
        e0 = add2(e0, e1);
        e2 = add2(e2, e3);
        e0 = add2(e0, e2);
        float tlo, thi;
        unpack2(e0, tlo, thi);
        float tot = tlo + thi;

        // one warp-wide cosine; 12 direct shfl.idx broadcasts (no smem)
        float arg = tot + cadd + (use_p ? pc : 0.0f);
        float cv  = __cosf(arg);

        float cr0 = __shfl_sync(0xffffffffu, cv, 0);
        float cr1 = __shfl_sync(0xffffffffu, cv, 4);
        float cr2 = __shfl_sync(0xffffffffu, cv, 8);
        float cr3 = __shfl_sync(0xffffffffu, cv, 12);
        float cz0 = __shfl_sync(0xffffffffu, cv, 1);
        float cz1 = __shfl_sync(0xffffffffu, cv, 5);
        float cz2 = __shfl_sync(0xffffffffu, cv, 9);
        float cz3 = __shfl_sync(0xffffffffu, cv, 13);
        float ch0 = __shfl_sync(0xffffffffu, cv, 16);
        float ch1 = __shfl_sync(0xffffffffu, cv, 20);
        float ch2 = __shfl_sync(0xffffffffu, cv, 24);
        float ch3 = __shfl_sync(0xffffffffu, cv, 28);

        // z-expectations after CNOT ring: (C1C2C3, C0C1, C0C1C2, C0C1C2C3)
        float rm = cr1 * cr2;
        float rA = cr0 * cr1, rB = cr0 * rm;
        float o_r = fmaf(rm * cr3, woRZ[0],
                    fmaf(rA, woRZ[1], fmaf(rB, woRZ[2],
                    fmaf(rB * cr3, woRZ[3], boRZ))));
        float Er = ex2f(-o_r);

        float hm = ch1 * ch2;
        float hA = ch0 * ch1, hB = ch0 * hm;
        float o_h = fmaf(hm * ch3, woHX[0],
                    fmaf(hA, woHX[1], fmaf(hB, woHX[2],
                    fmaf(hB * ch3, woHX[3], boHX))));

        float zm = cz1 * cz2;
        float zA = cz0 * cz1, zB = cz0 * zm;
        float o_z = fmaf(zm * cz3, woRZ[0],
                    fmaf(zA, woRZ[1], fmaf(zB, woRZ[2],
                    fmaf(zB * cz3, woRZ[3], boRZ))));
        float Ez = ex2f(-o_z);

        // u2 = 2*log2e*(o_x + o_h*r), r = sigmoid(o_r)
        float r  = rcpf(1.0f + Er);
        float u2 = fmaf(o_h, r, o_x);
        float Eu = ex2f(-u2);

        // h' = (Ez(1-Eu) + h(1+Eu)) / ((1+Eu)(1+Ez))
        float t2  = 1.0f + Eu;
        float num = fmaf(Ez, 1.0f - Eu, hj * t2);
        float den = t2 * (1.0f + Ez);
        hj = num * rcpf(den);

        orow[(size_t)t * HD] = hj;      // hidden_seq[b, t, j] (off-chain STG)
    }

    // h_last
    out[(size_t)NB * T_STEPS * HD + b * HD + j] = hj;
}

extern "C" void kernel_launch(void* const* d_in, const int* in_sizes, int n_in,
                              void* d_out, int out_size) {
    const float* x     = (const float*)d_in[0];
    const float* W_in  = (const float*)d_in[1];
    const float* b_in  = (const float*)d_in[2];
    const float* W_x   = (const float*)d_in[3];
    const float* b_x   = (const float*)d_in[4];
    const float* W_h   = (const float*)d_in[5];
    const float* b_h   = (const float*)d_in[6];
    const float* W_out = (const float*)d_in[7];
    const float* b_out = (const float*)d_in[8];
    const float* vqcw  = (const float*)d_in[9];
    float* out = (float*)d_out;

    qgru_prepass<<<PP_WARPS * 32 / 256, 256>>>(x, W_in, b_in, W_x, b_x, vqcw);
    qgru_seq<<<NB, HD>>>(W_in, W_h, b_h, W_out, b_out, vqcw, out);
}